// round 7
// baseline (speedup 1.0000x reference)
#include <cuda_runtime.h>
#include <cuda_bf16.h>
#include <math.h>
#include <stdint.h>

#define B_   32
#define C_   192
#define HH   56
#define WW   56
#define HW   3136
#define CO   384
#define K2   384
#define BN_EPS 1e-5f

// pre-converted bf16 hi/lo activations: channels 0..191 = x, 192..383 = xj
__device__ __nv_bfloat16 g_ah[(size_t)B_ * K2 * HW];
__device__ __nv_bfloat16 g_al[(size_t)B_ * K2 * HW];
__device__ __nv_bfloat16 g_wh[CO * K2];
__device__ __nv_bfloat16 g_wl[CO * K2];

// ===================== Stage 1: parity mins + bf16 hi/lo emit =====================
__global__ __launch_bounds__(256) void prep_kernel(const float* __restrict__ x) {
    __shared__ float img[HW];
    __shared__ float cmin[2][WW];
    __shared__ float rmin[HH][2];
    const int bc = blockIdx.x;
    const int b = bc / C_, c = bc % C_;
    const float* xp = x + (size_t)bc * HW;
    for (int i = threadIdx.x; i < HW; i += 256) img[i] = xp[i];
    __syncthreads();
    int t = threadIdx.x;
    if (t < 112) {
        int par = t / 56, q = t % 56;
        float m = 3.4e38f;
        #pragma unroll 7
        for (int r = par; r < HH; r += 2) m = fminf(m, img[r * WW + q]);
        cmin[par][q] = m;
    } else if (t < 224) {
        int t2 = t - 112;
        int par = t2 / 56, p = t2 % 56;
        float m = 3.4e38f;
        const float* row = &img[p * WW];
        #pragma unroll 7
        for (int q = par; q < WW; q += 2) m = fminf(m, row[q]);
        rmin[p][par] = m;
    }
    __syncthreads();
    __nv_bfloat16* xh = g_ah + ((size_t)b * K2 + c) * HW;
    __nv_bfloat16* xl = g_al + ((size_t)b * K2 + c) * HW;
    __nv_bfloat16* jh = g_ah + ((size_t)b * K2 + C_ + c) * HW;
    __nv_bfloat16* jl = g_al + ((size_t)b * K2 + C_ + c) * HW;
    for (int i2 = threadIdx.x; i2 < HW / 2; i2 += 256) {
        int i = i2 * 2;
        int p = i / WW, q = i - p * WW;        // q even, q+1 odd, same row p
        float v0 = img[i], v1 = img[i + 1];
        float j0 = v0 - fminf(cmin[p & 1][q],     rmin[p][0]);
        float j1 = v1 - fminf(cmin[p & 1][q + 1], rmin[p][1]);
        __nv_bfloat162 vh = __floats2bfloat162_rn(v0, v1);
        __nv_bfloat162 vl = __floats2bfloat162_rn(v0 - __bfloat162float(vh.x),
                                                  v1 - __bfloat162float(vh.y));
        __nv_bfloat162 jhv = __floats2bfloat162_rn(j0, j1);
        __nv_bfloat162 jlv = __floats2bfloat162_rn(j0 - __bfloat162float(jhv.x),
                                                   j1 - __bfloat162float(jhv.y));
        *(__nv_bfloat162*)(xh + i) = vh;
        *(__nv_bfloat162*)(xl + i) = vl;
        *(__nv_bfloat162*)(jh + i) = jhv;
        *(__nv_bfloat162*)(jl + i) = jlv;
    }
}

__global__ __launch_bounds__(256) void wconv_kernel(const float* __restrict__ Wc) {
    int idx = blockIdx.x * 256 + threadIdx.x;
    if (idx < CO * K2) {
        float w = Wc[idx];
        __nv_bfloat16 h = __float2bfloat16(w);
        g_wh[idx] = h;
        g_wl[idx] = __float2bfloat16(w - __bfloat162float(h));
    }
}

// ===================== Stage 2: cp.async-pipelined bf16 MMA GEMM =====================
// Per stage: AH [32k][272B] 8704, AL 8704, BH [128n][80B] 10240, BL 10240 = 37888 B
#define OFF_AH 0
#define OFF_AL 8704
#define OFF_BH 17408
#define OFF_BL 27648
#define BUFSZ  37888
#define STAGES 4
#define OFF_SC (STAGES * BUFSZ)
#define OFF_SH (OFF_SC + 512)
#define SMEM_TOTAL (OFF_SH + 512)

__device__ __forceinline__ uint32_t smem_u32(const void* p) {
    uint32_t a;
    asm("{ .reg .u64 t; cvta.to.shared.u64 t, %1; cvt.u32.u64 %0, t; }" : "=r"(a) : "l"(p));
    return a;
}
__device__ __forceinline__ void cp16(uint32_t dst, const void* src) {
    asm volatile("cp.async.cg.shared.global [%0], [%1], 16;" :: "r"(dst), "l"(src));
}
#define CP_COMMIT() asm volatile("cp.async.commit_group;" ::: "memory")
#define CP_WAIT2()  asm volatile("cp.async.wait_group 2;" ::: "memory")

__device__ __forceinline__ void ldsm_x4t(uint32_t* r, uint32_t a) {
    asm volatile("ldmatrix.sync.aligned.m8n8.x4.trans.shared.b16 {%0,%1,%2,%3}, [%4];"
        : "=r"(r[0]), "=r"(r[1]), "=r"(r[2]), "=r"(r[3]) : "r"(a));
}
__device__ __forceinline__ void ldsm_x4(uint32_t* r, uint32_t a) {
    asm volatile("ldmatrix.sync.aligned.m8n8.x4.shared.b16 {%0,%1,%2,%3}, [%4];"
        : "=r"(r[0]), "=r"(r[1]), "=r"(r[2]), "=r"(r[3]) : "r"(a));
}
__device__ __forceinline__ void mma_bf16(float* c, const uint32_t* a, const uint32_t* b) {
    asm volatile("mma.sync.aligned.m16n8k16.row.col.f32.bf16.bf16.f32 "
        "{%0,%1,%2,%3},{%4,%5,%6,%7},{%8,%9},{%0,%1,%2,%3};"
        : "+f"(c[0]), "+f"(c[1]), "+f"(c[2]), "+f"(c[3])
        : "r"(a[0]), "r"(a[1]), "r"(a[2]), "r"(a[3]), "r"(b[0]), "r"(b[1]));
}

__global__ __launch_bounds__(256, 1) void gemm_mma_kernel(
    const float* __restrict__ bconv, const float* __restrict__ gamma,
    const float* __restrict__ beta,  const float* __restrict__ rmean,
    const float* __restrict__ rvar,  float* __restrict__ out)
{
    extern __shared__ char sm[];
    const uint32_t sbase = smem_u32(sm);
    const int tid = threadIdx.x, wid = tid >> 5, lid = tid & 31;
    const int o0 = blockIdx.x * 128;
    const int g0 = blockIdx.y * 128;
    const int warp_m = wid >> 2, warp_n = wid & 3;

    float* scp = (float*)(sm + OFF_SC);
    float* shp = (float*)(sm + OFF_SH);
    if (tid < 128) {
        int o = o0 + tid;
        float sc = gamma[o] * rsqrtf(rvar[o] + BN_EPS);
        scp[tid] = sc;
        shp[tid] = (bconv[o] - rmean[o]) * sc + beta[o];
    }

    // ---- cp.async per-thread descriptors ----
    const int arow = tid >> 2;                 // 0..63 (32 hi + 32 lo k-rows)
    const int alo  = arow >> 5;
    const int ak   = arow & 31;
    const int ac0  = tid & 3;                  // chunk base; +4 per j (16 chunks of 16B)
    const __nv_bfloat16* asrc_t = alo ? g_al : g_ah;
    const uint32_t adst0 = (uint32_t)(alo ? OFF_AL : OFF_AH) + (uint32_t)ak * 272u;

    const int bn  = tid & 127;
    const int blo = tid >> 7;
    const __nv_bfloat16* bsrc_t = (blo ? g_wl : g_wh) + (size_t)(o0 + bn) * K2;
    const uint32_t bdst0 = (uint32_t)(blo ? OFF_BL : OFF_BH) + (uint32_t)bn * 80u;

    // precompute A global row bases for the 4 chunks this thread loads
    size_t a_off[4];
    #pragma unroll
    for (int j = 0; j < 4; j++) {
        int chunk = ac0 + 4 * j;
        int g = g0 + chunk * 8;                // 16B = 8 pixels; HW%8==0 so no straddle
        int bb = g / HW, p = g - bb * HW;
        a_off[j] = ((size_t)bb * K2) * HW + p; // + ch*HW added per stage
    }

    // ---- produce stage ci into buffer buf ----
    auto produce = [&](int ci, uint32_t buf) {
        int ch = ci * 32 + ak;
        #pragma unroll
        for (int j = 0; j < 4; j++) {
            int chunk = ac0 + 4 * j;
            cp16(buf + adst0 + (uint32_t)chunk * 16u,
                 asrc_t + a_off[j] + (size_t)ch * HW);
        }
        const __nv_bfloat16* bs = bsrc_t + ci * 32;
        #pragma unroll
        for (int j = 0; j < 4; j++)
            cp16(buf + bdst0 + (uint32_t)j * 16u, bs + j * 8);
    };

    float acc[4][4][4];
    #pragma unroll
    for (int i = 0; i < 4; i++)
        #pragma unroll
        for (int j = 0; j < 4; j++)
            #pragma unroll
            for (int e = 0; e < 4; e++) acc[i][j][e] = 0.f;

    const uint32_t a_row  = (uint32_t)((lid & 7) + ((lid >> 4) << 3));
    const uint32_t a_moff = (uint32_t)((warp_m * 64 + (((lid >> 3) & 1) << 3)) * 2);
    const uint32_t b_row  = (uint32_t)(warp_n * 32 + (lid & 7) + ((lid >> 4) << 3));
    const uint32_t b_koff = (uint32_t)(((lid >> 3) & 1) * 16);

    // prologue: stages 0..2
    #pragma unroll
    for (int s = 0; s < STAGES - 1; s++) {
        produce(s, sbase + (uint32_t)s * BUFSZ);
        CP_COMMIT();
    }

    for (int c = 0; c < 12; c++) {
        CP_WAIT2();          // stage c landed
        __syncthreads();     // all warps done with buffer (c-1)%4; stage c visible
        if (c + STAGES - 1 < 12)
            produce(c + STAGES - 1, sbase + (uint32_t)((c + STAGES - 1) & 3) * BUFSZ);
        CP_COMMIT();

        const uint32_t buf = sbase + (uint32_t)(c & 3) * BUFSZ;
        #pragma unroll
        for (int s = 0; s < 2; s++) {
            uint32_t ah[4][4], al[4][4], bh[2][4], bl[2][4];
            const uint32_t ab = buf + OFF_AH + ((uint32_t)(s * 16) + a_row) * 272u + a_moff;
            #pragma unroll
            for (int mf = 0; mf < 4; mf++) {
                ldsm_x4t(ah[mf], ab + (uint32_t)mf * 32u);
                ldsm_x4t(al[mf], ab + (OFF_AL - OFF_AH) + (uint32_t)mf * 32u);
            }
            const uint32_t bb = buf + OFF_BH + b_row * 80u + (uint32_t)(s * 32) + b_koff;
            #pragma unroll
            for (int q = 0; q < 2; q++) {
                ldsm_x4(bh[q], bb + (uint32_t)q * (16u * 80u));
                ldsm_x4(bl[q], bb + (OFF_BL - OFF_BH) + (uint32_t)q * (16u * 80u));
            }
            #pragma unroll
            for (int mf = 0; mf < 4; mf++) {
                #pragma unroll
                for (int nf = 0; nf < 4; nf++) {
                    const uint32_t* bhp = &bh[nf >> 1][(nf & 1) * 2];
                    const uint32_t* blp = &bl[nf >> 1][(nf & 1) * 2];
                    mma_bf16(acc[mf][nf], ah[mf], bhp);
                    mma_bf16(acc[mf][nf], al[mf], bhp);
                    mma_bf16(acc[mf][nf], ah[mf], blp);
                }
            }
        }
    }

    // ---- epilogue: BN + exact GELU ----
    #pragma unroll
    for (int mf = 0; mf < 4; mf++) {
        const int ml = warp_m * 64 + mf * 16 + (lid >> 2);
        #pragma unroll
        for (int half = 0; half < 2; half++) {
            int g = g0 + ml + half * 8;
            int bb = g / HW, p = g - bb * HW;
            float* orow = out + ((size_t)bb * CO + o0) * HW + p;
            #pragma unroll
            for (int nf = 0; nf < 4; nf++) {
                #pragma unroll
                for (int e = 0; e < 2; e++) {
                    int n = warp_n * 32 + nf * 8 + (lid & 3) * 2 + e;
                    float y = acc[mf][nf][half * 2 + e] * scp[n] + shp[n];
                    y = 0.5f * y * (1.0f + erff(y * 0.70710678118654752f));
                    orow[(size_t)n * HW] = y;
                }
            }
        }
    }
}

extern "C" void kernel_launch(void* const* d_in, const int* in_sizes, int n_in,
                              void* d_out, int out_size) {
    const float* x     = (const float*)d_in[0];
    const float* Wc    = (const float*)d_in[1];
    const float* bconv = (const float*)d_in[2];
    const float* gamma = (const float*)d_in[3];
    const float* beta  = (const float*)d_in[4];
    const float* rmean = (const float*)d_in[5];
    const float* rvar  = (const float*)d_in[6];
    float* out = (float*)d_out;

    prep_kernel<<<B_ * C_, 256>>>(x);
    wconv_kernel<<<(CO * K2 + 255) / 256, 256>>>(Wc);

    cudaFuncSetAttribute(gemm_mma_kernel,
                         cudaFuncAttributeMaxDynamicSharedMemorySize, SMEM_TOTAL);
    dim3 grid(CO / 128, HW * B_ / 128);   // (3, 784)
    gemm_mma_kernel<<<grid, 256, SMEM_TOTAL>>>(bconv, gamma, beta, rmean, rvar, out);
}

// round 8
// speedup vs baseline: 1.1967x; 1.1967x over previous
#include <cuda_runtime.h>
#include <cuda_bf16.h>
#include <math.h>
#include <stdint.h>

#define B_   32
#define C_   192
#define HH   56
#define WW   56
#define HW   3136
#define CO   384
#define K2   384
#define BN_EPS 1e-5f

// pre-converted bf16 hi/lo activations: channels 0..191 = x, 192..383 = xj
__device__ __nv_bfloat16 g_ah[(size_t)B_ * K2 * HW];
__device__ __nv_bfloat16 g_al[(size_t)B_ * K2 * HW];
__device__ __nv_bfloat16 g_wh[CO * K2];
__device__ __nv_bfloat16 g_wl[CO * K2];

// ===================== Stage 1: parity mins + bf16 hi/lo emit =====================
__global__ __launch_bounds__(256) void prep_kernel(const float* __restrict__ x) {
    __shared__ float img[HW];
    __shared__ float cmin[2][WW];
    __shared__ float rmin[HH][2];
    const int bc = blockIdx.x;
    const int b = bc / C_, c = bc % C_;
    const float* xp = x + (size_t)bc * HW;
    for (int i = threadIdx.x; i < HW; i += 256) img[i] = xp[i];
    __syncthreads();
    int t = threadIdx.x;
    if (t < 112) {
        int par = t / 56, q = t % 56;
        float m = 3.4e38f;
        #pragma unroll 7
        for (int r = par; r < HH; r += 2) m = fminf(m, img[r * WW + q]);
        cmin[par][q] = m;
    } else if (t < 224) {
        int t2 = t - 112;
        int par = t2 / 56, p = t2 % 56;
        float m = 3.4e38f;
        const float* row = &img[p * WW];
        #pragma unroll 7
        for (int q = par; q < WW; q += 2) m = fminf(m, row[q]);
        rmin[p][par] = m;
    }
    __syncthreads();
    __nv_bfloat16* xh = g_ah + ((size_t)b * K2 + c) * HW;
    __nv_bfloat16* xl = g_al + ((size_t)b * K2 + c) * HW;
    __nv_bfloat16* jh = g_ah + ((size_t)b * K2 + C_ + c) * HW;
    __nv_bfloat16* jl = g_al + ((size_t)b * K2 + C_ + c) * HW;
    for (int i2 = threadIdx.x; i2 < HW / 2; i2 += 256) {
        int i = i2 * 2;
        int p = i / WW, q = i - p * WW;
        float v0 = img[i], v1 = img[i + 1];
        float j0 = v0 - fminf(cmin[p & 1][q],     rmin[p][0]);
        float j1 = v1 - fminf(cmin[p & 1][q + 1], rmin[p][1]);
        __nv_bfloat162 vh = __floats2bfloat162_rn(v0, v1);
        __nv_bfloat162 vl = __floats2bfloat162_rn(v0 - __bfloat162float(vh.x),
                                                  v1 - __bfloat162float(vh.y));
        __nv_bfloat162 jhv = __floats2bfloat162_rn(j0, j1);
        __nv_bfloat162 jlv = __floats2bfloat162_rn(j0 - __bfloat162float(jhv.x),
                                                   j1 - __bfloat162float(jhv.y));
        *(__nv_bfloat162*)(xh + i) = vh;
        *(__nv_bfloat162*)(xl + i) = vl;
        *(__nv_bfloat162*)(jh + i) = jhv;
        *(__nv_bfloat162*)(jl + i) = jlv;
    }
}

__global__ __launch_bounds__(256) void wconv_kernel(const float* __restrict__ Wc) {
    int idx = blockIdx.x * 256 + threadIdx.x;
    if (idx < CO * K2) {
        float w = Wc[idx];
        __nv_bfloat16 h = __float2bfloat16(w);
        g_wh[idx] = h;
        g_wl[idx] = __float2bfloat16(w - __bfloat162float(h));
    }
}

// ===================== Stage 2: cp.async-pipelined bf16 MMA GEMM, 16 warps =====================
// Per stage: AH [32k][272B] 8704, AL 8704, BH [128n][80B] 10240, BL 10240 = 37888 B
#define OFF_AH 0
#define OFF_AL 8704
#define OFF_BH 17408
#define OFF_BL 27648
#define BUFSZ  37888
#define STAGES 4
#define OFF_SC (STAGES * BUFSZ)
#define OFF_SH (OFF_SC + 512)
#define SMEM_TOTAL (OFF_SH + 512)

__device__ __forceinline__ uint32_t smem_u32(const void* p) {
    uint32_t a;
    asm("{ .reg .u64 t; cvta.to.shared.u64 t, %1; cvt.u32.u64 %0, t; }" : "=r"(a) : "l"(p));
    return a;
}
__device__ __forceinline__ void cp16(uint32_t dst, const void* src) {
    asm volatile("cp.async.cg.shared.global [%0], [%1], 16;" :: "r"(dst), "l"(src));
}
#define CP_COMMIT() asm volatile("cp.async.commit_group;" ::: "memory")
#define CP_WAIT2()  asm volatile("cp.async.wait_group 2;" ::: "memory")

__device__ __forceinline__ void ldsm_x4t(uint32_t* r, uint32_t a) {
    asm volatile("ldmatrix.sync.aligned.m8n8.x4.trans.shared.b16 {%0,%1,%2,%3}, [%4];"
        : "=r"(r[0]), "=r"(r[1]), "=r"(r[2]), "=r"(r[3]) : "r"(a));
}
__device__ __forceinline__ void ldsm_x4(uint32_t* r, uint32_t a) {
    asm volatile("ldmatrix.sync.aligned.m8n8.x4.shared.b16 {%0,%1,%2,%3}, [%4];"
        : "=r"(r[0]), "=r"(r[1]), "=r"(r[2]), "=r"(r[3]) : "r"(a));
}
__device__ __forceinline__ void mma_bf16(float* c, const uint32_t* a, const uint32_t* b) {
    asm volatile("mma.sync.aligned.m16n8k16.row.col.f32.bf16.bf16.f32 "
        "{%0,%1,%2,%3},{%4,%5,%6,%7},{%8,%9},{%0,%1,%2,%3};"
        : "+f"(c[0]), "+f"(c[1]), "+f"(c[2]), "+f"(c[3])
        : "r"(a[0]), "r"(a[1]), "r"(a[2]), "r"(a[3]), "r"(b[0]), "r"(b[1]));
}

__global__ __launch_bounds__(512, 1) void gemm_mma_kernel(
    const float* __restrict__ bconv, const float* __restrict__ gamma,
    const float* __restrict__ beta,  const float* __restrict__ rmean,
    const float* __restrict__ rvar,  float* __restrict__ out)
{
    extern __shared__ char sm[];
    const uint32_t sbase = smem_u32(sm);
    const int tid = threadIdx.x, wid = tid >> 5, lid = tid & 31;
    const int o0 = blockIdx.x * 128;
    const int g0 = blockIdx.y * 128;
    const int warp_m = wid >> 2, warp_n = wid & 3;   // 4x4 warp grid, 32x32 tiles

    float* scp = (float*)(sm + OFF_SC);
    float* shp = (float*)(sm + OFF_SH);
    if (tid < 128) {
        int o = o0 + tid;
        float sc = gamma[o] * rsqrtf(rvar[o] + BN_EPS);
        scp[tid] = sc;
        shp[tid] = (bconv[o] - rmean[o]) * sc + beta[o];
    }

    // ---- cp.async per-thread descriptors (512 threads, 4x16B each) ----
    const int arow = tid >> 3;                 // 0..63 (32 hi + 32 lo k-rows)
    const int alo  = arow >> 5;
    const int ak   = arow & 31;
    const int ac0  = tid & 7;                  // chunk base; chunks ac0, ac0+8
    const __nv_bfloat16* asrc_t = alo ? g_al : g_ah;
    const uint32_t adst0 = (uint32_t)(alo ? OFF_AL : OFF_AH) + (uint32_t)ak * 272u;

    const int bn  = tid >> 2;                  // 0..127
    const int bc4 = tid & 3;                   // 16B chunk within 64B row
    const __nv_bfloat16* bsrc_h = g_wh + (size_t)(o0 + bn) * K2;
    const __nv_bfloat16* bsrc_l = g_wl + (size_t)(o0 + bn) * K2;
    const uint32_t bdst_h = (uint32_t)OFF_BH + (uint32_t)bn * 80u + (uint32_t)bc4 * 16u;
    const uint32_t bdst_l = (uint32_t)OFF_BL + (uint32_t)bn * 80u + (uint32_t)bc4 * 16u;

    size_t a_off[2];
    #pragma unroll
    for (int j = 0; j < 2; j++) {
        int chunk = ac0 + 8 * j;
        int g = g0 + chunk * 8;                // 16B = 8 pixels, HW%8==0 so no straddle
        int bb = g / HW, p = g - bb * HW;
        a_off[j] = ((size_t)bb * K2) * HW + p;
    }

    auto produce = [&](int ci, uint32_t buf) {
        int ch = ci * 32 + ak;
        #pragma unroll
        for (int j = 0; j < 2; j++) {
            int chunk = ac0 + 8 * j;
            cp16(buf + adst0 + (uint32_t)chunk * 16u,
                 asrc_t + a_off[j] + (size_t)ch * HW);
        }
        cp16(buf + bdst_h, bsrc_h + ci * 32 + bc4 * 8);
        cp16(buf + bdst_l, bsrc_l + ci * 32 + bc4 * 8);
    };

    float acc[2][4][4];
    #pragma unroll
    for (int i = 0; i < 2; i++)
        #pragma unroll
        for (int j = 0; j < 4; j++)
            #pragma unroll
            for (int e = 0; e < 4; e++) acc[i][j][e] = 0.f;

    const uint32_t a_row  = (uint32_t)((lid & 7) + ((lid >> 4) << 3));
    const uint32_t a_moff = (uint32_t)((warp_m * 32 + (((lid >> 3) & 1) << 3)) * 2);
    const uint32_t b_row  = (uint32_t)(warp_n * 32 + (lid & 7) + ((lid >> 4) << 3));
    const uint32_t b_koff = (uint32_t)(((lid >> 3) & 1) * 16);

    #pragma unroll
    for (int s = 0; s < STAGES - 1; s++) {
        produce(s, sbase + (uint32_t)s * BUFSZ);
        CP_COMMIT();
    }

    for (int c = 0; c < 12; c++) {
        CP_WAIT2();
        __syncthreads();
        if (c + STAGES - 1 < 12)
            produce(c + STAGES - 1, sbase + (uint32_t)((c + STAGES - 1) & 3) * BUFSZ);
        CP_COMMIT();

        const uint32_t buf = sbase + (uint32_t)(c & 3) * BUFSZ;
        #pragma unroll
        for (int s = 0; s < 2; s++) {
            uint32_t ah[2][4], al[2][4], bh[2][4], bl[2][4];
            const uint32_t ab = buf + OFF_AH + ((uint32_t)(s * 16) + a_row) * 272u + a_moff;
            #pragma unroll
            for (int mf = 0; mf < 2; mf++) {
                ldsm_x4t(ah[mf], ab + (uint32_t)mf * 32u);
                ldsm_x4t(al[mf], ab + (OFF_AL - OFF_AH) + (uint32_t)mf * 32u);
            }
            const uint32_t bba = buf + OFF_BH + b_row * 80u + (uint32_t)(s * 32) + b_koff;
            #pragma unroll
            for (int q = 0; q < 2; q++) {
                ldsm_x4(bh[q], bba + (uint32_t)q * (16u * 80u));
                ldsm_x4(bl[q], bba + (OFF_BL - OFF_BH) + (uint32_t)q * (16u * 80u));
            }
            // product-major order: same-acc reuse distance = 4 MMAs
            #pragma unroll
            for (int mf = 0; mf < 2; mf++) {
                #pragma unroll
                for (int nf = 0; nf < 4; nf++)
                    mma_bf16(acc[mf][nf], ah[mf], &bh[nf >> 1][(nf & 1) * 2]);
                #pragma unroll
                for (int nf = 0; nf < 4; nf++)
                    mma_bf16(acc[mf][nf], al[mf], &bh[nf >> 1][(nf & 1) * 2]);
                #pragma unroll
                for (int nf = 0; nf < 4; nf++)
                    mma_bf16(acc[mf][nf], ah[mf], &bl[nf >> 1][(nf & 1) * 2]);
            }
        }
    }

    // ---- epilogue: BN + exact GELU ----
    #pragma unroll
    for (int mf = 0; mf < 2; mf++) {
        const int ml = warp_m * 32 + mf * 16 + (lid >> 2);
        #pragma unroll
        for (int half = 0; half < 2; half++) {
            int g = g0 + ml + half * 8;
            int bb = g / HW, p = g - bb * HW;
            float* orow = out + ((size_t)bb * CO + o0) * HW + p;
            #pragma unroll
            for (int nf = 0; nf < 4; nf++) {
                #pragma unroll
                for (int e = 0; e < 2; e++) {
                    int n = warp_n * 32 + nf * 8 + (lid & 3) * 2 + e;
                    float y = acc[mf][nf][half * 2 + e] * scp[n] + shp[n];
                    y = 0.5f * y * (1.0f + erff(y * 0.70710678118654752f));
                    orow[(size_t)n * HW] = y;
                }
            }
        }
    }
}

extern "C" void kernel_launch(void* const* d_in, const int* in_sizes, int n_in,
                              void* d_out, int out_size) {
    const float* x     = (const float*)d_in[0];
    const float* Wc    = (const float*)d_in[1];
    const float* bconv = (const float*)d_in[2];
    const float* gamma = (const float*)d_in[3];
    const float* beta  = (const float*)d_in[4];
    const float* rmean = (const float*)d_in[5];
    const float* rvar  = (const float*)d_in[6];
    float* out = (float*)d_out;

    prep_kernel<<<B_ * C_, 256>>>(x);
    wconv_kernel<<<(CO * K2 + 255) / 256, 256>>>(Wc);

    cudaFuncSetAttribute(gemm_mma_kernel,
                         cudaFuncAttributeMaxDynamicSharedMemorySize, SMEM_TOTAL);
    dim3 grid(CO / 128, HW * B_ / 128);   // (3, 784)
    gemm_mma_kernel<<<grid, 512, SMEM_TOTAL>>>(bconv, gamma, beta, rmean, rvar, out);
}